// round 7
// baseline (speedup 1.0000x reference)
#include <cuda_runtime.h>

// ---------------------------------------------------------------------------
// GCN 5-layer forward on GB300.
// k_zero resets state; k_csr is a persistent-grid kernel doing the whole CSR
// build (hist -> offset scan -> scatter) with device-wide barriers, plus the
// first dense transform. Hot chain: fused gather+next-transform kernels
// (float4, 8-lane groups, 4 independent LDG.128 per group per iteration).
// Launch order places a 32->32 k_fused at launch index 3 for ncu sampling.
// ---------------------------------------------------------------------------

#define NN 100000
#define NE 1600000
#define CSR_BLOCKS 592          // 148 SMs x 4 blocks, co-residency guaranteed

__device__ int   g_deg[NN];         // edge in-degree (without self loop)
__device__ int   g_off[NN];         // start offsets, mutated to end by scatter
__device__ int   g_rows[NE];        // CSR row (source) indices grouped by col
__device__ float g_bufA[NN * 32];   // dinv-scaled transformed rows (ping)
__device__ float g_bufB[NN * 32];   // (pong)
__device__ int   g_alloc;           // offset range allocator
__device__ int   g_is64;            // 1 if edge_index is int64, 0 if int32
__device__ unsigned g_barcnt;       // grid barrier arrival counter
__device__ unsigned g_barsense;     // grid barrier generation

// Zero degrees, reset allocator + barrier state, probe edge dtype.
__global__ void k_zero(const long long* __restrict__ ei) {
    int i = blockIdx.x * blockDim.x + threadIdx.x;
    if (i < NN) g_deg[i] = 0;
    if (blockIdx.x == 0) {
        __shared__ int bad;
        if (threadIdx.x == 0) { bad = 0; g_alloc = 0; g_barcnt = 0; g_barsense = 0; }
        __syncthreads();
        long long v = ei[threadIdx.x];
        if (v < 0 || v >= NN) bad = 1;
        __syncthreads();
        if (threadIdx.x == 0) g_is64 = bad ? 0 : 1;
    }
}

// Device-wide barrier (all gridDim.x blocks co-resident by construction).
__device__ __forceinline__ void grid_barrier(unsigned target) {
    __syncthreads();
    if (threadIdx.x == 0) {
        __threadfence();
        unsigned old = atomicAdd(&g_barcnt, 1u);
        if (old == gridDim.x - 1) {
            g_barcnt = 0;
            __threadfence();
            *(volatile unsigned*)&g_barsense = target;
        } else {
            while (*(volatile unsigned*)&g_barsense < target) __nanosleep(64);
        }
        __threadfence();
    }
    __syncthreads();
}

// Persistent CSR build + first transform.
// Phase A: degree histogram. Phase B: offset scan + transform1. Phase C: scatter.
__global__ __launch_bounds__(256, 4)
void k_csr(const int* __restrict__ ei32, const float* __restrict__ x,
           const float* __restrict__ W1) {
    int tid  = threadIdx.x;
    int gtid = blockIdx.x * 256 + tid;
    int nthr = gridDim.x * 256;
    int is64 = g_is64;

    // --- Phase A: histogram of destination degrees ---
    for (int i = gtid; i < NE; i += nthr) {
        int c = is64 ? ei32[2 * (NE + i)] : ei32[NE + i];
        if ((unsigned)c < NN) atomicAdd(&g_deg[c], 1);
    }
    grid_barrier(1);

    // --- Phase B: offsets (256-chunk scan + atomic base alloc) ---
    __shared__ int s[256];
    __shared__ int sbase;
    const int nchunks = (NN + 255) / 256;
    for (int chunk = blockIdx.x; chunk < nchunks; chunk += gridDim.x) {
        int n = chunk * 256 + tid;
        int v = (n < NN) ? g_deg[n] : 0;
        s[tid] = v;
        __syncthreads();
#pragma unroll
        for (int d = 1; d < 256; d <<= 1) {
            int y = (tid >= d) ? s[tid - d] : 0;
            __syncthreads();
            s[tid] += y;
            __syncthreads();
        }
        if (tid == 255) sbase = atomicAdd(&g_alloc, s[255]);
        __syncthreads();
        if (n < NN) g_off[n] = sbase + s[tid] - v;
        __syncthreads();
    }

    // --- Phase B (cont.): transform1  g_bufA = dinv * (x @ W1), 8 -> 32 ---
    __shared__ float sW[8 * 32];
    for (int i = tid; i < 8 * 32; i += 256) sW[i] = W1[i];
    __syncthreads();
    {
        int lane = tid & 31;
        int wid  = gtid >> 5;
        int nw   = nthr >> 5;
        for (int node = wid; node < NN; node += nw) {
            float hv = (lane < 8) ? x[node * 8 + lane] : 0.f;
            float acc = 0.f;
#pragma unroll
            for (int k = 0; k < 8; ++k)
                acc += __shfl_sync(0xffffffffu, hv, k) * sW[k * 32 + lane];
            float dinv = rsqrtf((float)(g_deg[node] + 1));
            g_bufA[node * 32 + lane] = acc * dinv;
        }
    }
    grid_barrier(2);

    // --- Phase C: scatter rows into per-destination buckets ---
    for (int i = gtid; i < NE; i += nthr) {
        int r = is64 ? ei32[2 * i] : ei32[i];
        int c = is64 ? ei32[2 * (NE + i)] : ei32[NE + i];
        if ((unsigned)c < NN && (unsigned)r < NN) {
            int p = atomicAdd(&g_off[c], 1);   // g_off becomes "end" pointer
            g_rows[p] = r;
        }
    }
}

// Fused: aggregate src (dout=32) -> h = dinv*sum + bias, then next-layer
// transform g2 = dinv*(h @ W) written with row stride OS. AtoB selects the
// ping-pong direction in device code. Warp per node; 8-lane groups own edge
// residues mod 4; each iteration issues 4 independent LDG.128 per group.
template <int DNEXT, int OS, bool AtoB>
__global__ void k_fused(const float* __restrict__ bias,
                        const float* __restrict__ W) {
    const float* gsrc = AtoB ? g_bufA : g_bufB;
    float*       gdst = AtoB ? g_bufB : g_bufA;

    __shared__ float sW[32 * DNEXT];
    for (int i = threadIdx.x; i < 32 * DNEXT; i += blockDim.x) sW[i] = W[i];
    __syncthreads();

    int warp = (blockIdx.x * blockDim.x + threadIdx.x) >> 5;
    int lane = threadIdx.x & 31;
    if (warp >= NN) return;

    int grp = lane >> 3;          // edge residue within a 4-edge pack
    int fl  = lane & 7;           // float4 column within the 32-float row
    int end   = g_off[warp];
    int cnt   = g_deg[warp];
    int start = end - cnt;

    const float4* src4 = (const float4*)gsrc;

    // Self-loop term contributed once by group 0.
    float4 acc = make_float4(0.f, 0.f, 0.f, 0.f);
    if (grp == 0) acc = src4[warp * 8 + fl];

    int e = start + grp;
    for (; e + 12 < end; e += 16) {           // 16 lines in flight per warp
        int r0 = g_rows[e];
        int r1 = g_rows[e + 4];
        int r2 = g_rows[e + 8];
        int r3 = g_rows[e + 12];
        float4 v0 = src4[r0 * 8 + fl];
        float4 v1 = src4[r1 * 8 + fl];
        float4 v2 = src4[r2 * 8 + fl];
        float4 v3 = src4[r3 * 8 + fl];
        acc.x += (v0.x + v1.x) + (v2.x + v3.x);
        acc.y += (v0.y + v1.y) + (v2.y + v3.y);
        acc.z += (v0.z + v1.z) + (v2.z + v3.z);
        acc.w += (v0.w + v1.w) + (v2.w + v3.w);
    }
    for (; e < end; e += 4) {
        int r = g_rows[e];
        float4 v = src4[r * 8 + fl];
        acc.x += v.x; acc.y += v.y; acc.z += v.z; acc.w += v.w;
    }

    // Reduce across the 4 groups: every lane gets the column sums.
#pragma unroll
    for (int d = 8; d <= 16; d <<= 1) {
        acc.x += __shfl_xor_sync(0xffffffffu, acc.x, d);
        acc.y += __shfl_xor_sync(0xffffffffu, acc.y, d);
        acc.z += __shfl_xor_sync(0xffffffffu, acc.z, d);
        acc.w += __shfl_xor_sync(0xffffffffu, acc.w, d);
    }

    // Redistribute: lane j takes feature j (component j&3 of float4 j>>2).
    int srcl = lane >> 2;
    float t0 = __shfl_sync(0xffffffffu, acc.x, srcl);
    float t1 = __shfl_sync(0xffffffffu, acc.y, srcl);
    float t2 = __shfl_sync(0xffffffffu, acc.z, srcl);
    float t3 = __shfl_sync(0xffffffffu, acc.w, srcl);
    int c = lane & 3;
    float s = (c == 0) ? t0 : (c == 1) ? t1 : (c == 2) ? t2 : t3;

    float dinv = rsqrtf((float)(cnt + 1));
    float h = s * dinv + bias[lane];          // this layer's output feature

    // Next layer transform: g2_j = dinv * sum_k h_k * W[k][j]
    float a2 = 0.f;
#pragma unroll
    for (int k = 0; k < 32; ++k) {
        float hk = __shfl_sync(0xffffffffu, h, k);
        if (lane < DNEXT) a2 += hk * sW[k * DNEXT + lane];
    }
    if (lane < DNEXT) gdst[warp * OS + lane] = a2 * dinv;
}

// Final aggregation over stride-4 rows in g_bufA (dout=3): 1 lane per edge.
__global__ void k_final(float* __restrict__ out,
                        const float* __restrict__ bias) {
    int warp = (blockIdx.x * blockDim.x + threadIdx.x) >> 5;
    int lane = threadIdx.x & 31;
    if (warp >= NN) return;

    int end   = g_off[warp];
    int cnt   = g_deg[warp];
    int start = end - cnt;

    const float4* src4 = (const float4*)g_bufA;
    float4 acc = make_float4(0.f, 0.f, 0.f, 0.f);
    if (lane == 0) {                           // self loop
        float4 v = src4[warp];
        acc.x = v.x; acc.y = v.y; acc.z = v.z;
    }

    for (int e = start + lane; e < end; e += 32) {
        int r = g_rows[e];
        float4 v = src4[r];
        acc.x += v.x; acc.y += v.y; acc.z += v.z;
    }
#pragma unroll
    for (int d = 1; d <= 16; d <<= 1) {
        acc.x += __shfl_xor_sync(0xffffffffu, acc.x, d);
        acc.y += __shfl_xor_sync(0xffffffffu, acc.y, d);
        acc.z += __shfl_xor_sync(0xffffffffu, acc.z, d);
    }
    if (lane == 0) {
        float dinv = rsqrtf((float)(cnt + 1));
        out[warp * 3 + 0] = acc.x * dinv + bias[0];
        out[warp * 3 + 1] = acc.y * dinv + bias[1];
        out[warp * 3 + 2] = acc.z * dinv + bias[2];
    }
}

extern "C" void kernel_launch(void* const* d_in, const int* in_sizes, int n_in,
                              void* d_out, int out_size) {
    const float* x    = (const float*)d_in[0];
    const int*   ei32 = (const int*)d_in[1];
    const float* W1 = (const float*)d_in[2];
    const float* b1 = (const float*)d_in[3];
    const float* W2 = (const float*)d_in[4];
    const float* b2 = (const float*)d_in[5];
    const float* W3 = (const float*)d_in[6];
    const float* b3 = (const float*)d_in[7];
    const float* W4 = (const float*)d_in[8];
    const float* b4 = (const float*)d_in[9];
    const float* W5 = (const float*)d_in[10];
    const float* b5 = (const float*)d_in[11];

    const int TB = 256;
    dim3 nodeGrid((NN + TB - 1) / TB);
    dim3 warpGrid((NN * 32 + TB - 1) / TB);  // warp per node

    k_zero<<<nodeGrid, TB>>>((const long long*)ei32);      // launch 0
    k_csr<<<CSR_BLOCKS, TB>>>(ei32, x, W1);                // launch 1 (CSR + x->A)
    k_fused<32, 32, true ><<<warpGrid, TB>>>(b1, W2);      // launch 2: A -> B
    k_fused<32, 32, false><<<warpGrid, TB>>>(b2, W3);      // launch 3: B -> A (profiled)
    k_fused<32, 32, true ><<<warpGrid, TB>>>(b3, W4);      // launch 4: A -> B
    k_fused<3, 4, false><<<warpGrid, TB>>>(b4, W5);        // launch 5: B -> A (stride 4)
    k_final<<<warpGrid, TB>>>((float*)d_out, b5);          // launch 6
}

// round 9
// speedup vs baseline: 1.0768x; 1.0768x over previous
#include <cuda_runtime.h>

// ---------------------------------------------------------------------------
// GCN 5-layer forward on GB300.
// k_zero resets state; k_csr (persistent grid) builds CSR (hist -> offset
// scan -> scatter) with device-wide barriers and does the first transform.
// Hot chain: k_fused gathers + next-layer transform. Each warp owns 8 nodes,
// holds W in 32 registers, gathers with float4/8-lane groups (4 independent
// LDG.128 per iter), butterfly-reduces, and does the matvec via one STS.128
// + 8 broadcast LDS.128 against register W (epilogue MIO ~19 ops vs ~76).
// ---------------------------------------------------------------------------

#define NN 100000
#define NE 1600000
#define CSR_BLOCKS 592          // 148 SMs x 4 blocks, co-residency guaranteed
#define NPW 8                   // nodes per warp in k_fused

__device__ int   g_deg[NN];         // edge in-degree (without self loop)
__device__ int   g_off[NN];         // start offsets, mutated to end by scatter
__device__ int   g_rows[NE];        // CSR row (source) indices grouped by col
__device__ float g_bufA[NN * 32];   // dinv-scaled transformed rows (ping)
__device__ float g_bufB[NN * 32];   // (pong)
__device__ int   g_alloc;           // offset range allocator
__device__ int   g_is64;            // 1 if edge_index is int64, 0 if int32
__device__ unsigned g_barcnt;       // grid barrier arrival counter
__device__ unsigned g_barsense;     // grid barrier generation

// Zero degrees, reset allocator + barrier state, probe edge dtype.
__global__ void k_zero(const long long* __restrict__ ei) {
    int i = blockIdx.x * blockDim.x + threadIdx.x;
    if (i < NN) g_deg[i] = 0;
    if (blockIdx.x == 0) {
        __shared__ int bad;
        if (threadIdx.x == 0) { bad = 0; g_alloc = 0; g_barcnt = 0; g_barsense = 0; }
        __syncthreads();
        long long v = ei[threadIdx.x];
        if (v < 0 || v >= NN) bad = 1;
        __syncthreads();
        if (threadIdx.x == 0) g_is64 = bad ? 0 : 1;
    }
}

// Device-wide barrier (all gridDim.x blocks co-resident by construction).
__device__ __forceinline__ void grid_barrier(unsigned target) {
    __syncthreads();
    if (threadIdx.x == 0) {
        __threadfence();
        unsigned old = atomicAdd(&g_barcnt, 1u);
        if (old == gridDim.x - 1) {
            g_barcnt = 0;
            __threadfence();
            *(volatile unsigned*)&g_barsense = target;
        } else {
            while (*(volatile unsigned*)&g_barsense < target) __nanosleep(64);
        }
        __threadfence();
    }
    __syncthreads();
}

// Persistent CSR build + first transform.
__global__ __launch_bounds__(256, 4)
void k_csr(const int* __restrict__ ei32, const float* __restrict__ x,
           const float* __restrict__ W1) {
    int tid  = threadIdx.x;
    int gtid = blockIdx.x * 256 + tid;
    int nthr = gridDim.x * 256;
    int is64 = g_is64;

    // --- Phase A: histogram of destination degrees ---
    for (int i = gtid; i < NE; i += nthr) {
        int c = is64 ? ei32[2 * (NE + i)] : ei32[NE + i];
        if ((unsigned)c < NN) atomicAdd(&g_deg[c], 1);
    }
    grid_barrier(1);

    // --- Phase B: offsets (256-chunk scan + atomic base alloc) ---
    __shared__ int s[256];
    __shared__ int sbase;
    const int nchunks = (NN + 255) / 256;
    for (int chunk = blockIdx.x; chunk < nchunks; chunk += gridDim.x) {
        int n = chunk * 256 + tid;
        int v = (n < NN) ? g_deg[n] : 0;
        s[tid] = v;
        __syncthreads();
#pragma unroll
        for (int d = 1; d < 256; d <<= 1) {
            int y = (tid >= d) ? s[tid - d] : 0;
            __syncthreads();
            s[tid] += y;
            __syncthreads();
        }
        if (tid == 255) sbase = atomicAdd(&g_alloc, s[255]);
        __syncthreads();
        if (n < NN) g_off[n] = sbase + s[tid] - v;
        __syncthreads();
    }

    // --- Phase B (cont.): transform1  g_bufA = dinv * (x @ W1), 8 -> 32 ---
    __shared__ float sW[8 * 32];
    for (int i = tid; i < 8 * 32; i += 256) sW[i] = W1[i];
    __syncthreads();
    {
        int lane = tid & 31;
        int wid  = gtid >> 5;
        int nw   = nthr >> 5;
        for (int node = wid; node < NN; node += nw) {
            float hv = (lane < 8) ? x[node * 8 + lane] : 0.f;
            float acc = 0.f;
#pragma unroll
            for (int k = 0; k < 8; ++k)
                acc += __shfl_sync(0xffffffffu, hv, k) * sW[k * 32 + lane];
            float dinv = rsqrtf((float)(g_deg[node] + 1));
            g_bufA[node * 32 + lane] = acc * dinv;
        }
    }
    grid_barrier(2);

    // --- Phase C: scatter rows into per-destination buckets ---
    for (int i = gtid; i < NE; i += nthr) {
        int r = is64 ? ei32[2 * i] : ei32[i];
        int c = is64 ? ei32[2 * (NE + i)] : ei32[NE + i];
        if ((unsigned)c < NN && (unsigned)r < NN) {
            int p = atomicAdd(&g_off[c], 1);   // g_off becomes "end" pointer
            g_rows[p] = r;
        }
    }
}

// Fused: per warp, NPW consecutive nodes. Aggregate src (dim 32) -> h, then
// g2 = dinv*(h @ W) with W register-resident (loaded once per warp).
template <int DNEXT, int OS, bool AtoB>
__global__ __launch_bounds__(256)
void k_fused(const float* __restrict__ bias, const float* __restrict__ W) {
    const float* gsrc = AtoB ? g_bufA : g_bufB;
    float*       gdst = AtoB ? g_bufB : g_bufA;

    __shared__ float4 sh_h[8][8];     // per-warp h row (32 floats)

    int wid   = (blockIdx.x * blockDim.x + threadIdx.x) >> 5;
    int wloc  = threadIdx.x >> 5;
    int lane  = threadIdx.x & 31;
    int node0 = wid * NPW;
    if (node0 >= NN) return;

    // W[k][lane] into registers, once per warp (amortized over NPW nodes).
    float Wr[32];
#pragma unroll
    for (int k = 0; k < 32; ++k)
        Wr[k] = (lane < DNEXT) ? W[k * DNEXT + lane] : 0.f;

    int grp = lane >> 3;              // edge residue within a 4-edge pack
    int fl  = lane & 7;               // float4 column within the row
    float4 bias4 = ((const float4*)bias)[fl];   // bias for features 4fl..4fl+3

    // Prefetch offsets/degrees for the NPW nodes (2 coalesced loads).
    int myoff = 0, mydeg = 0;
    if (lane < NPW) {
        myoff = g_off[node0 + lane];
        mydeg = g_deg[node0 + lane];
    }

    const float4* src4 = (const float4*)gsrc;

#pragma unroll 1
    for (int n = 0; n < NPW; ++n) {
        int node = node0 + n;
        int end  = __shfl_sync(0xffffffffu, myoff, n);
        int cnt  = __shfl_sync(0xffffffffu, mydeg, n);
        int start = end - cnt;

        // Self-loop term contributed once by group 0.
        float4 acc = make_float4(0.f, 0.f, 0.f, 0.f);
        if (grp == 0) acc = src4[node * 8 + fl];

        int e = start + grp;
        for (; e + 12 < end; e += 16) {       // 16 lines in flight per warp
            int r0 = g_rows[e];
            int r1 = g_rows[e + 4];
            int r2 = g_rows[e + 8];
            int r3 = g_rows[e + 12];
            float4 v0 = src4[r0 * 8 + fl];
            float4 v1 = src4[r1 * 8 + fl];
            float4 v2 = src4[r2 * 8 + fl];
            float4 v3 = src4[r3 * 8 + fl];
            acc.x += (v0.x + v1.x) + (v2.x + v3.x);
            acc.y += (v0.y + v1.y) + (v2.y + v3.y);
            acc.z += (v0.z + v1.z) + (v2.z + v3.z);
            acc.w += (v0.w + v1.w) + (v2.w + v3.w);
        }
        for (; e < end; e += 4) {
            int r = g_rows[e];
            float4 v = src4[r * 8 + fl];
            acc.x += v.x; acc.y += v.y; acc.z += v.z; acc.w += v.w;
        }

        // Butterfly across the 4 groups: all lanes hold the column sums.
#pragma unroll
        for (int d = 8; d <= 16; d <<= 1) {
            acc.x += __shfl_xor_sync(0xffffffffu, acc.x, d);
            acc.y += __shfl_xor_sync(0xffffffffu, acc.y, d);
            acc.z += __shfl_xor_sync(0xffffffffu, acc.z, d);
            acc.w += __shfl_xor_sync(0xffffffffu, acc.w, d);
        }

        float dinv = rsqrtf((float)(cnt + 1));
        float4 h4;
        h4.x = acc.x * dinv + bias4.x;
        h4.y = acc.y * dinv + bias4.y;
        h4.z = acc.z * dinv + bias4.z;
        h4.w = acc.w * dinv + bias4.w;

        if (grp == 0) sh_h[wloc][fl] = h4;    // one STS.128 per fl
        __syncwarp();

        // Matvec: 8 broadcast LDS.128 + 32 FFMA against register W.
        float a2 = 0.f;
#pragma unroll
        for (int c = 0; c < 8; ++c) {
            float4 hc = sh_h[wloc][c];
            a2 += hc.x * Wr[4 * c] + hc.y * Wr[4 * c + 1]
                + hc.z * Wr[4 * c + 2] + hc.w * Wr[4 * c + 3];
        }
        __syncwarp();                          // before next node overwrites

        if (lane < DNEXT) gdst[node * OS + lane] = a2 * dinv;
    }
}

// Final aggregation over stride-4 rows in g_bufA (dout=3): 1 lane per edge.
__global__ void k_final(float* __restrict__ out,
                        const float* __restrict__ bias) {
    int warp = (blockIdx.x * blockDim.x + threadIdx.x) >> 5;
    int lane = threadIdx.x & 31;
    if (warp >= NN) return;

    int end   = g_off[warp];
    int cnt   = g_deg[warp];
    int start = end - cnt;

    const float4* src4 = (const float4*)g_bufA;
    float4 acc = make_float4(0.f, 0.f, 0.f, 0.f);
    if (lane == 0) {                           // self loop
        float4 v = src4[warp];
        acc.x = v.x; acc.y = v.y; acc.z = v.z;
    }

    for (int e = start + lane; e < end; e += 32) {
        int r = g_rows[e];
        float4 v = src4[r];
        acc.x += v.x; acc.y += v.y; acc.z += v.z;
    }
#pragma unroll
    for (int d = 1; d <= 16; d <<= 1) {
        acc.x += __shfl_xor_sync(0xffffffffu, acc.x, d);
        acc.y += __shfl_xor_sync(0xffffffffu, acc.y, d);
        acc.z += __shfl_xor_sync(0xffffffffu, acc.z, d);
    }
    if (lane == 0) {
        float dinv = rsqrtf((float)(cnt + 1));
        out[warp * 3 + 0] = acc.x * dinv + bias[0];
        out[warp * 3 + 1] = acc.y * dinv + bias[1];
        out[warp * 3 + 2] = acc.z * dinv + bias[2];
    }
}

extern "C" void kernel_launch(void* const* d_in, const int* in_sizes, int n_in,
                              void* d_out, int out_size) {
    const float* x    = (const float*)d_in[0];
    const int*   ei32 = (const int*)d_in[1];
    const float* W1 = (const float*)d_in[2];
    const float* b1 = (const float*)d_in[3];
    const float* W2 = (const float*)d_in[4];
    const float* b2 = (const float*)d_in[5];
    const float* W3 = (const float*)d_in[6];
    const float* b3 = (const float*)d_in[7];
    const float* W4 = (const float*)d_in[8];
    const float* b4 = (const float*)d_in[9];
    const float* W5 = (const float*)d_in[10];
    const float* b5 = (const float*)d_in[11];

    const int TB = 256;
    dim3 nodeGrid((NN + TB - 1) / TB);
    dim3 warpGrid((NN * 32 + TB - 1) / TB);              // warp per node
    const int nwarps = (NN + NPW - 1) / NPW;             // k_fused warps
    dim3 fusedGrid((nwarps * 32 + TB - 1) / TB);

    k_zero<<<nodeGrid, TB>>>((const long long*)ei32);     // launch 0
    k_csr<<<CSR_BLOCKS, TB>>>(ei32, x, W1);               // launch 1 (CSR + x->A)
    k_fused<32, 32, true ><<<fusedGrid, TB>>>(b1, W2);    // launch 2: A -> B
    k_fused<32, 32, false><<<fusedGrid, TB>>>(b2, W3);    // launch 3: B -> A (profiled)
    k_fused<32, 32, true ><<<fusedGrid, TB>>>(b3, W4);    // launch 4: A -> B
    k_fused<3, 4, false><<<fusedGrid, TB>>>(b4, W5);      // launch 5: B -> A (stride 4)
    k_final<<<warpGrid, TB>>>((float*)d_out, b5);         // launch 6
}